// round 14
// baseline (speedup 1.0000x reference)
#include <cuda_runtime.h>
#include <math.h>

// FNO spectral conv: truncated separable DFTs + mirror/conjugate/quarter symmetries.
// B=8, H=W=256, CIN=COUT=32, M1=M2=16.
typedef unsigned long long u64;
typedef ulonglong2 u64x2;

// Tables / transposed weights / scratch (device globals).
__device__ __align__(16) float4 g_tab4[256];    // (cos, cos, sin, sin)
__device__ __align__(8)  float2 g_tab2[256];    // (cos, sin)
__device__ __align__(16) float4 g_stw[520];     // k5 twiddles [w][j]: (c2j, c2j1, s2j, s2j1)
__device__ __align__(16) float  g_wtr[524288];  // [blk][m1][kx][ci][co]
__device__ __align__(16) float  g_wti[524288];
__device__ __align__(16) float  g_Tre[1048576]; // [b][kx][h][c]
__device__ __align__(16) float  g_Tim[1048576];
__device__ __align__(16) float  g_Xre[131072];  // [p*16+kx][b*32+c]
__device__ __align__(16) float  g_Xim[131072];
__device__ __align__(16) float  g_Gre[1048576]; // [b][h][kx][co]
__device__ __align__(16) float  g_Gim[1048576];

__device__ __forceinline__ u64 pack2(float lo, float hi) {
    u64 r; asm("mov.b64 %0,{%1,%2};" : "=l"(r) : "f"(lo), "f"(hi)); return r;
}
__device__ __forceinline__ float2 unpack2(u64 v) {
    float2 f; asm("mov.b64 {%0,%1},%2;" : "=f"(f.x), "=f"(f.y) : "l"(v)); return f;
}
__device__ __forceinline__ u64 ffma2(u64 a, u64 b, u64 c) {
    u64 d; asm("fma.rn.f32x2 %0,%1,%2,%3;" : "=l"(d) : "l"(a), "l"(b), "l"(c)); return d;
}
__device__ __forceinline__ u64 fmul2(u64 a, u64 b) {
    u64 d; asm("mul.rn.f32x2 %0,%1,%2;" : "=l"(d) : "l"(a), "l"(b)); return d;
}
__device__ __forceinline__ u64 fadd2(u64 a, u64 b) {
    u64 d; asm("add.rn.f32x2 %0,%1,%2;" : "=l"(d) : "l"(a), "l"(b)); return d;
}
__device__ __forceinline__ u64 fsub2(u64 a, u64 b) {
    u64 d; asm("sub.rn.f32x2 %0,%1,%2;" : "=l"(d) : "l"(a), "l"(b)); return d;
}

// ---------------------------------------------------------------------------
// KA: fused launch, 128 threads.
//   blocks [0,2048):    forward w-DFT with mirror + quarter-wave folding.
//   blocks [2048,2560): tiled weight transpose -> [blk][m1][kx][ci][co].
//   block  2560:        twiddle tables (incl. k5 parity-pair stw table).
// ---------------------------------------------------------------------------
__global__ __launch_bounds__(128) void kA(const float* __restrict__ x,
                                          const float* __restrict__ wr,
                                          const float* __restrict__ wi) {
    const int bid = blockIdx.x, t = threadIdx.x;

    if (bid < 2048) {
        __shared__ __align__(16) float4 seE[64 * 8], seO[64 * 8];
        __shared__ __align__(16) float4 soE[64 * 8], soO[64 * 8];
        __shared__ __align__(16) float4 stab[256];
        __shared__ __align__(16) float4 sx0[8], sx64[8], sx128[8], sx192[8];
        const float4* xb = (const float4*)(x + (size_t)bid * 8192);

        for (int i = t; i < 256; i += 128) {
            float s, c; sincospif((float)i * (1.0f / 128.0f), &s, &c);
            stab[i] = make_float4(c, c, s, s);
        }
        for (int i = t; i < 504; i += 128) {
            const int w = 1 + (i >> 3), cq = i & 7;
            const float4 a = xb[w * 8 + cq];            // x[w]
            const float4 b = xb[(256 - w) * 8 + cq];    // x[256-w]
            const float4 c = xb[(128 - w) * 8 + cq];    // x[128-w]
            const float4 d = xb[(128 + w) * 8 + cq];    // x[128+w]
            const int ix = w * 8 + cq;
            seE[ix] = make_float4(a.x + b.x + c.x + d.x, a.y + b.y + c.y + d.y,
                                  a.z + b.z + c.z + d.z, a.w + b.w + c.w + d.w);
            seO[ix] = make_float4(a.x + b.x - c.x - d.x, a.y + b.y - c.y - d.y,
                                  a.z + b.z - c.z - d.z, a.w + b.w - c.w - d.w);
            soE[ix] = make_float4(a.x - b.x - c.x + d.x, a.y - b.y - c.y + d.y,
                                  a.z - b.z - c.z + d.z, a.w - b.w - c.w + d.w);
            soO[ix] = make_float4(a.x - b.x + c.x - d.x, a.y - b.y + c.y - d.y,
                                  a.z - b.z + c.z - d.z, a.w - b.w + c.w - d.w);
        }
        if (t < 8) {
            sx0[t] = xb[t]; sx64[t] = xb[512 + t];
            sx128[t] = xb[1024 + t]; sx192[t] = xb[1536 + t];
        }
        __syncthreads();

        const int kx = t >> 3, cq = t & 7;
        const int odd = kx & 1;
        const float s64 = (kx & 2) ? -1.0f : 1.0f;
        const u64 s64v = pack2(s64, s64);
        const u64x2 X0   = *(const u64x2*)&sx0[cq];
        const u64x2 X64  = *(const u64x2*)&sx64[cq];
        const u64x2 X128 = *(const u64x2*)&sx128[cq];
        const u64x2 X192 = *(const u64x2*)&sx192[cq];
        u64 re0, re1, im0, im1;
        if (!odd) {
            re0 = ffma2(fadd2(X64.x, X192.x), s64v, fadd2(X0.x, X128.x));
            re1 = ffma2(fadd2(X64.y, X192.y), s64v, fadd2(X0.y, X128.y));
            im0 = 0; im1 = 0;
        } else {
            re0 = fsub2(X0.x, X128.x);
            re1 = fsub2(X0.y, X128.y);
            im0 = fmul2(fsub2(X64.x, X192.x), s64v);
            im1 = fmul2(fsub2(X64.y, X192.y), s64v);
        }
        const float4* pe = (odd ? seO : seE) + cq;
        const float4* po = (odd ? soO : soE) + cq;
        int m = kx;
#pragma unroll 4
        for (int w = 1; w < 64; w++) {
            const u64x2 ev = *(const u64x2*)(pe + w * 8);
            const u64x2 ov = *(const u64x2*)(po + w * 8);
            const u64x2 tv = *(const u64x2*)&stab[m];
            m = (m + kx) & 255;
            re0 = ffma2(ev.x, tv.x, re0); re1 = ffma2(ev.y, tv.x, re1);
            im0 = ffma2(ov.x, tv.y, im0); im1 = ffma2(ov.y, tv.y, im1);
        }
        const int b = bid >> 8, h = bid & 255;
        const size_t o4 = ((size_t)((b * 16 + kx) * 256 + h)) * 8 + cq;
        const float2 r0 = unpack2(re0), r1 = unpack2(re1);
        ((float4*)g_Tre)[o4] = make_float4(r0.x, r0.y, r1.x, r1.y);
        const u64 n1 = pack2(-1.0f, -1.0f);
        const float2 i0 = unpack2(fmul2(im0, n1)), i1 = unpack2(fmul2(im1, n1));
        ((float4*)g_Tim)[o4] = make_float4(i0.x, i0.y, i1.x, i1.y);

    } else if (bid < 2560) {
        // ---- tiled transpose: [ci*32+co][m1*16+kx] -> [m1*16+kx][ci*32+co] ----
        __shared__ float sw[32][33], sv[32][33];
        const int tt = bid - 2048;
        const int blkw = tt >> 8, tile = tt & 255;
        const int tr = tile >> 3, tc = tile & 7;
        const int rr = t >> 5, c = t & 31;
        const float* srcR = wr + blkw * 262144;
        const float* srcI = wi + blkw * 262144;
#pragma unroll
        for (int ph = 0; ph < 8; ph++) {
            const int rl = ph * 4 + rr;
            const int row = tr * 32 + rl, col = tc * 32 + c;
            sw[rl][c] = srcR[row * 256 + col];
            sv[rl][c] = srcI[row * 256 + col];
        }
        __syncthreads();
        float* dR = g_wtr + blkw * 262144;
        float* dI = g_wti + blkw * 262144;
#pragma unroll
        for (int ph = 0; ph < 8; ph++) {
            const int cl = ph * 4 + rr;
            const int dcol = tc * 32 + cl, drow = tr * 32 + c;
            dR[dcol * 1024 + drow] = sw[c][cl];
            dI[dcol * 1024 + drow] = sv[c][cl];
        }
    } else {
        for (int i = t; i < 256; i += 128) {
            float s, c; sincospif((float)i * (1.0f / 128.0f), &s, &c);
            g_tab4[i] = make_float4(c, c, s, s);
            g_tab2[i] = make_float2(c, s);
        }
        for (int i = t; i < 520; i += 128) {
            const int w = i >> 3, j = i & 7;
            float s0, c0, s1, c1;
            sincospif((float)((2 * j * w) & 255) * (1.0f / 128.0f), &s0, &c0);
            sincospif((float)(((2 * j + 1) * w) & 255) * (1.0f / 128.0f), &s1, &c1);
            g_stw[i] = make_float4(c0, c1, s0, s1);
        }
    }
}

// ---------------------------------------------------------------------------
// K2: forward DFT over h, conjugate-pair generators + quarter-wave folding.
// grid (16 kx, 2 ch, 8 b) = 256 blocks, 136 threads: p = t>>3 (0..16), cp = t&7.
// ---------------------------------------------------------------------------
__global__ __launch_bounds__(136) void k2_dft_h() {
    __shared__ __align__(16) float4 sAe[64 * 8], sAo[64 * 8];   // {cosdata(Er), sindata(Oi)}
    __shared__ __align__(16) float4 sBe[64 * 8], sBo[64 * 8];   // {cosdata(Ei), sindata(-Or)}
    __shared__ __align__(16) float4 stab[256];
    __shared__ __align__(16) float4 sT0[8], sT128[8], sA64[8], sB64[8];
    const int t = threadIdx.x;
    const int kx = blockIdx.x, ch = blockIdx.y, b = blockIdx.z;
    const float* srcR = g_Tre + ((size_t)(b * 16 + kx) * 256) * 32 + ch * 16;
    const float* srcI = g_Tim + ((size_t)(b * 16 + kx) * 256) * 32 + ch * 16;

    for (int i = t; i < 256; i += 136) stab[i] = g_tab4[i];
    for (int i = t; i < 504; i += 136) {
        const int h = 1 + (i >> 3), cp = i & 7;
        const float2 ar = *(const float2*)&srcR[h * 32 + cp * 2];
        const float2 br = *(const float2*)&srcR[(256 - h) * 32 + cp * 2];
        const float2 ai = *(const float2*)&srcI[h * 32 + cp * 2];
        const float2 bi = *(const float2*)&srcI[(256 - h) * 32 + cp * 2];
        const float2 cr = *(const float2*)&srcR[(128 - h) * 32 + cp * 2];
        const float2 dr = *(const float2*)&srcR[(128 + h) * 32 + cp * 2];
        const float2 ci = *(const float2*)&srcI[(128 - h) * 32 + cp * 2];
        const float2 di = *(const float2*)&srcI[(128 + h) * 32 + cp * 2];
        const float2 Er  = make_float2(ar.x + br.x, ar.y + br.y);
        const float2 Erp = make_float2(cr.x + dr.x, cr.y + dr.y);
        const float2 Oi  = make_float2(ai.x - bi.x, ai.y - bi.y);
        const float2 Oip = make_float2(ci.x - di.x, ci.y - di.y);
        const float2 Ei  = make_float2(ai.x + bi.x, ai.y + bi.y);
        const float2 Eip = make_float2(ci.x + di.x, ci.y + di.y);
        const float2 nOr  = make_float2(br.x - ar.x, br.y - ar.y);
        const float2 nOrp = make_float2(dr.x - cr.x, dr.y - cr.y);
        const int ix = h * 8 + cp;
        sAe[ix] = make_float4(Er.x + Erp.x, Er.y + Erp.y, Oi.x - Oip.x, Oi.y - Oip.y);
        sAo[ix] = make_float4(Er.x - Erp.x, Er.y - Erp.y, Oi.x + Oip.x, Oi.y + Oip.y);
        sBe[ix] = make_float4(Ei.x + Eip.x, Ei.y + Eip.y, nOr.x - nOrp.x, nOr.y - nOrp.y);
        sBo[ix] = make_float4(Ei.x - Eip.x, Ei.y - Eip.y, nOr.x + nOrp.x, nOr.y + nOrp.y);
    }
    if (t < 8) {
        sT0[t]   = make_float4(srcR[t * 2], srcR[t * 2 + 1], srcI[t * 2], srcI[t * 2 + 1]);
        sT128[t] = make_float4(srcR[4096 + t * 2], srcR[4096 + t * 2 + 1],
                               srcI[4096 + t * 2], srcI[4096 + t * 2 + 1]);
        const float r64a = srcR[2048 + t * 2],  r64b = srcR[2048 + t * 2 + 1];
        const float r92a = srcR[6144 + t * 2],  r92b = srcR[6144 + t * 2 + 1];
        const float i64a = srcI[2048 + t * 2],  i64b = srcI[2048 + t * 2 + 1];
        const float i92a = srcI[6144 + t * 2],  i92b = srcI[6144 + t * 2 + 1];
        sA64[t] = make_float4(r64a + r92a, r64b + r92b, i64a - i92a, i64b - i92b);
        sB64[t] = make_float4(i64a + i92a, i64b + i92b, r92a - r64a, r92b - r64b);
    }
    __syncthreads();

    const int p = t >> 3, cp = t & 7;
    const int odd = p & 1;
    const float s64 = (p & 2) ? -1.0f : 1.0f;
    const u64 s64v = pack2(s64, s64);
    const u64x2 t0 = *(const u64x2*)&sT0[cp];
    const u64x2 t1 = *(const u64x2*)&sT128[cp];
    const u64x2 a64 = *(const u64x2*)&sA64[cp];
    const u64x2 b64 = *(const u64x2*)&sB64[cp];
    u64 C1, C2, C3, C4;
    if (!odd) {
        C1 = ffma2(a64.x, s64v, fadd2(t0.x, t1.x)); C2 = 0;
        C3 = ffma2(b64.x, s64v, fadd2(t0.y, t1.y)); C4 = 0;
    } else {
        C1 = fsub2(t0.x, t1.x); C2 = fmul2(a64.y, s64v);
        C3 = fsub2(t0.y, t1.y); C4 = fmul2(b64.y, s64v);
    }
    const float4* pA = (odd ? sAo : sAe) + cp;
    const float4* pB = (odd ? sBo : sBe) + cp;
    int m = p;
#pragma unroll 4
    for (int h = 1; h < 64; h++) {
        const u64x2 A  = *(const u64x2*)(pA + h * 8);
        const u64x2 Bv = *(const u64x2*)(pB + h * 8);
        const u64x2 tv = *(const u64x2*)&stab[m];
        m = (m + p) & 255;
        C1 = ffma2(A.x, tv.x, C1);  C2 = ffma2(A.y, tv.y, C2);
        C3 = ffma2(Bv.x, tv.x, C3); C4 = ffma2(Bv.y, tv.y, C4);
    }
    const int c = ch * 16 + cp * 2;
    if (p < 16) {                                   // X(+p) -> row p
        const size_t ix = (size_t)(p * 16 + kx) * 256 + b * 32 + c;
        *(float2*)&g_Xre[ix] = unpack2(fadd2(C1, C2));
        *(float2*)&g_Xim[ix] = unpack2(fadd2(C3, C4));
    }
    if (p >= 1) {                                   // X(-p) -> row 32-p
        const size_t ix = (size_t)((32 - p) * 16 + kx) * 256 + b * 32 + c;
        *(float2*)&g_Xre[ix] = unpack2(fsub2(C1, C2));
        *(float2*)&g_Xim[ix] = unpack2(fsub2(C3, C4));
    }
}

// ---------------------------------------------------------------------------
// K34: fused channel mix + inverse h-DFT per (kx, b, co-half) tile.
// grid (16 kx, 8 b, 2 ch) = 256 blocks, 512 threads.
//   Phase 1 (mix): thread = p(32) x col(16): Y[p][col] = sum_ci X[p][ci]*W.
//   Phase 2 (iDFT h, parity-split quad): thread = hl(64) x cp(8);
//   h = hl+1 in 1..64; quad rows {h, 256-h, 128-h, 128+h}; h==64 also rows 0,128.
// ---------------------------------------------------------------------------
__global__ __launch_bounds__(512) void k34() {
    __shared__ __align__(16) float4 stab[256];
    __shared__ __align__(16) float sXr[1024], sXi[1024];   // [p][ci]  (all 32 ci)
    __shared__ __align__(16) float sYr[512], sYi[512];     // [p][col] (16 local co)
    const int t = threadIdx.x;
    const int kx = blockIdx.x, b = blockIdx.y, ch = blockIdx.z;

    if (t < 256) stab[t] = g_tab4[t];
    for (int i = t; i < 1024; i += 512) {
        const int p = i >> 5, c = i & 31;
        const size_t src = (size_t)(p * 16 + kx) * 256 + b * 32 + c;
        sXr[i] = g_Xre[src];
        sXi[i] = g_Xim[src];
    }
    __syncthreads();

    // ---- Phase 1: channel mix (co half) ----
    {
        const int p = t >> 4, col = t & 15;
        const int co = ch * 16 + col;
        const int blk = p >> 4, m1 = p & 15;
        const int base = ((blk * 16 + m1) * 16 + kx) * 1024 + co;
        float accR = 0.f, accI = 0.f;
#pragma unroll
        for (int ci = 0; ci < 32; ci++) {
            const float Xr = sXr[p * 32 + ci], Xi = sXi[p * 32 + ci];
            const float Wr = g_wtr[base + ci * 32];
            const float Wi = g_wti[base + ci * 32];
            accR += Xr * Wr - Xi * Wi;
            accI += Xr * Wi + Xi * Wr;
        }
        sYr[t] = accR;
        sYi[t] = accI;
    }
    __syncthreads();

    // ---- Phase 2: inverse DFT over h, parity-split quad outputs ----
    const int hl = t >> 3, cp = t & 7;
    const int h = hl + 1;                        // 1..64
    const int yoff = cp * 2;                     // within 16-wide local row
    u64 RcE = 0, RcO = 0, RsE = 0, RsO = 0, IsE = 0, IsO = 0, IcE = 0, IcO = 0;

    int m = 0;                                   // p=0..15: f = p
#pragma unroll 1
    for (int p = 0; p < 16; p += 2) {
        const u64x2 t0 = *(const u64x2*)&stab[m]; m = (m + h) & 255;
        const u64x2 t1 = *(const u64x2*)&stab[m]; m = (m + h) & 255;
        const u64 Yr0 = *(const u64*)&sYr[p * 16 + yoff];
        const u64 Yi0 = *(const u64*)&sYi[p * 16 + yoff];
        const u64 Yr1 = *(const u64*)&sYr[(p + 1) * 16 + yoff];
        const u64 Yi1 = *(const u64*)&sYi[(p + 1) * 16 + yoff];
        RcE = ffma2(Yr0, t0.x, RcE); RsE = ffma2(Yi0, t0.y, RsE);
        IsE = ffma2(Yr0, t0.y, IsE); IcE = ffma2(Yi0, t0.x, IcE);
        RcO = ffma2(Yr1, t1.x, RcO); RsO = ffma2(Yi1, t1.y, RsO);
        IsO = ffma2(Yr1, t1.y, IsO); IcO = ffma2(Yi1, t1.x, IcO);
    }
    m = (4096 - 16 * h) & 255;                   // p=16..31: f = p-32 (same parity as p)
#pragma unroll 1
    for (int p = 16; p < 32; p += 2) {
        const u64x2 t0 = *(const u64x2*)&stab[m]; m = (m + h) & 255;
        const u64x2 t1 = *(const u64x2*)&stab[m]; m = (m + h) & 255;
        const u64 Yr0 = *(const u64*)&sYr[p * 16 + yoff];
        const u64 Yi0 = *(const u64*)&sYi[p * 16 + yoff];
        const u64 Yr1 = *(const u64*)&sYr[(p + 1) * 16 + yoff];
        const u64 Yi1 = *(const u64*)&sYi[(p + 1) * 16 + yoff];
        RcE = ffma2(Yr0, t0.x, RcE); RsE = ffma2(Yi0, t0.y, RsE);
        IsE = ffma2(Yr0, t0.y, IsE); IcE = ffma2(Yi0, t0.x, IcE);
        RcO = ffma2(Yr1, t1.x, RcO); RsO = ffma2(Yi1, t1.y, RsO);
        IsO = ffma2(Yr1, t1.y, IsO); IcO = ffma2(Yi1, t1.x, IcO);
    }

    const u64 Rcs = fadd2(RcE, RcO), Rcd = fsub2(RcE, RcO);
    const u64 Rss = fadd2(RsE, RsO), Rsd = fsub2(RsE, RsO);
    const u64 Iss = fadd2(IsE, IsO), Isd = fsub2(IsE, IsO);
    const u64 Ics = fadd2(IcE, IcO), Icd = fsub2(IcE, IcO);

    const float sc = (kx == 0 ? 1.0f : 2.0f) * (1.0f / 65536.0f);
    const u64 scl = pack2(sc, sc);
    const size_t rowbase = ((size_t)(b * 256) * 16 + kx) * 32 + ch * 16 + cp * 2;

    *(float2*)&g_Gre[rowbase + (size_t)h * 512] = unpack2(fmul2(fsub2(Rcs, Rss), scl));
    *(float2*)&g_Gim[rowbase + (size_t)h * 512] = unpack2(fmul2(fadd2(Iss, Ics), scl));
    *(float2*)&g_Gre[rowbase + (size_t)(128 + h) * 512] = unpack2(fmul2(fsub2(Rcd, Rsd), scl));
    *(float2*)&g_Gim[rowbase + (size_t)(128 + h) * 512] = unpack2(fmul2(fadd2(Isd, Icd), scl));
    if (h < 64) {
        *(float2*)&g_Gre[rowbase + (size_t)(256 - h) * 512] = unpack2(fmul2(fadd2(Rcs, Rss), scl));
        *(float2*)&g_Gim[rowbase + (size_t)(256 - h) * 512] = unpack2(fmul2(fsub2(Ics, Iss), scl));
        *(float2*)&g_Gre[rowbase + (size_t)(128 - h) * 512] = unpack2(fmul2(fadd2(Rcd, Rsd), scl));
        *(float2*)&g_Gim[rowbase + (size_t)(128 - h) * 512] = unpack2(fmul2(fsub2(Icd, Isd), scl));
    } else {
        u64 ZrE = 0, ZrO = 0, ZiE = 0, ZiO = 0;
#pragma unroll 1
        for (int p = 0; p < 32; p += 2) {
            const u64 Yr0 = *(const u64*)&sYr[p * 16 + yoff];
            const u64 Yi0 = *(const u64*)&sYi[p * 16 + yoff];
            const u64 Yr1 = *(const u64*)&sYr[(p + 1) * 16 + yoff];
            const u64 Yi1 = *(const u64*)&sYi[(p + 1) * 16 + yoff];
            ZrE = fadd2(ZrE, Yr0); ZiE = fadd2(ZiE, Yi0);
            ZrO = fadd2(ZrO, Yr1); ZiO = fadd2(ZiO, Yi1);
        }
        *(float2*)&g_Gre[rowbase] = unpack2(fmul2(fadd2(ZrE, ZrO), scl));
        *(float2*)&g_Gim[rowbase] = unpack2(fmul2(fadd2(ZiE, ZiO), scl));
        *(float2*)&g_Gre[rowbase + (size_t)128 * 512] = unpack2(fmul2(fsub2(ZrE, ZrO), scl));
        *(float2*)&g_Gim[rowbase + (size_t)128 * 512] = unpack2(fmul2(fsub2(ZiE, ZiO), scl));
    }
}

// ---------------------------------------------------------------------------
// K5: inverse DFT over w, parity k-pairs: lane0 = even k, lane1 = odd k.
// One (C,S) accumulation (8+8 ffma2, 8 LDS.128) -> FOUR outputs:
//   out(w) = Cs-Ss, out(256-w) = Cs+Ss, out(128+w) = Cd-Sd, out(128-w) = Cd+Sd
// grid 2048 (b*256+h), 256 threads = co(32) x wg(8).
// ---------------------------------------------------------------------------
__device__ __forceinline__ void k5_body(const float4* stw, const u64* Gr, const u64* Gi,
                                        float* ob, int w, int co) {
    u64 C = 0, S = 0;
    const u64x2* tw = (const u64x2*)&stw[w * 8];
#pragma unroll
    for (int j = 0; j < 8; j++) {
        const u64x2 v = tw[j];
        C = ffma2(Gr[j], v.x, C);
        S = ffma2(Gi[j], v.y, S);
    }
    const float2 c2 = unpack2(C), s2 = unpack2(S);
    const float Cs = c2.x + c2.y, Cd = c2.x - c2.y;
    const float Ss = s2.x + s2.y, Sd = s2.x - s2.y;
    ob[w * 32 + co]                   = Cs - Ss;
    ob[(((256 - w) & 255)) * 32 + co] = Cs + Ss;
    ob[(128 + w) * 32 + co]           = Cd - Sd;
    ob[(128 - w) * 32 + co]           = Cd + Sd;
}

__global__ __launch_bounds__(256) void k5_idft_w(float* __restrict__ out) {
    __shared__ __align__(16) float4 stw[65 * 8];   // [w][j] (c2j, c2j1, s2j, s2j1)
    const int t = threadIdx.x;
    const int blk = blockIdx.x;                     // b*256 + h

    for (int i = t; i < 520; i += 256) stw[i] = g_stw[i];
    const int co = t & 31, wg = t >> 5;
    u64 Gr[8], Gi[8];
    {
        const float* pr = g_Gre + (size_t)blk * 512 + co;
        const float* pi = g_Gim + (size_t)blk * 512 + co;
#pragma unroll
        for (int j = 0; j < 8; j++) {
            Gr[j] = pack2(pr[(2 * j) * 32], pr[(2 * j + 1) * 32]);
            Gi[j] = pack2(pi[(2 * j) * 32], pi[(2 * j + 1) * 32]);
        }
    }
    __syncthreads();

    float* ob = out + (size_t)blk * 8192;
#pragma unroll 2
    for (int j = 0; j < 8; j++) k5_body(stw, Gr, Gi, ob, wg + 8 * j, co);
    if (wg == 0) k5_body(stw, Gr, Gi, ob, 64, co);
}

// ---------------------------------------------------------------------------
extern "C" void kernel_launch(void* const* d_in, const int* in_sizes, int n_in,
                              void* d_out, int out_size) {
    (void)n_in; (void)out_size; (void)in_sizes;
    const float* x  = (const float*)d_in[0];
    const float* wr = (const float*)d_in[1];
    const float* wi = (const float*)d_in[2];
    float* out = (float*)d_out;

    kA<<<2561, 128>>>(x, wr, wi);
    k2_dft_h<<<dim3(16, 2, 8), 136>>>();
    k34<<<dim3(16, 8, 2), 512>>>();
    k5_idft_w<<<2048, 256>>>(out);
}

// round 15
// speedup vs baseline: 1.0333x; 1.0333x over previous
#include <cuda_runtime.h>
#include <math.h>

// FNO spectral conv: truncated separable DFTs + mirror/conjugate/quarter symmetries.
// B=8, H=W=256, CIN=COUT=32, M1=M2=16.
typedef unsigned long long u64;
typedef ulonglong2 u64x2;

// Tables / transposed weights / scratch (device globals).
__device__ __align__(16) float4 g_tab4[256];    // (cos, cos, sin, sin)
__device__ __align__(8)  float2 g_tab2[256];    // (cos, sin)
__device__ __align__(16) float4 g_stw[520];     // k5 twiddles [w][j]: (c2j, c2j1, s2j, s2j1)
__device__ __align__(16) float  g_wtr[524288];  // [blk][m1][kx][ci][co]
__device__ __align__(16) float  g_wti[524288];
__device__ __align__(16) float  g_Tre[1048576]; // [b][kx][h][c]
__device__ __align__(16) float  g_Tim[1048576];
__device__ __align__(16) float  g_Xre[131072];  // [p*16+kx][b*32+c]
__device__ __align__(16) float  g_Xim[131072];
__device__ __align__(16) float  g_Gre[1048576]; // [b][h][kx][co]
__device__ __align__(16) float  g_Gim[1048576];

__device__ __forceinline__ u64 pack2(float lo, float hi) {
    u64 r; asm("mov.b64 %0,{%1,%2};" : "=l"(r) : "f"(lo), "f"(hi)); return r;
}
__device__ __forceinline__ float2 unpack2(u64 v) {
    float2 f; asm("mov.b64 {%0,%1},%2;" : "=f"(f.x), "=f"(f.y) : "l"(v)); return f;
}
__device__ __forceinline__ u64 ffma2(u64 a, u64 b, u64 c) {
    u64 d; asm("fma.rn.f32x2 %0,%1,%2,%3;" : "=l"(d) : "l"(a), "l"(b), "l"(c)); return d;
}
__device__ __forceinline__ u64 fmul2(u64 a, u64 b) {
    u64 d; asm("mul.rn.f32x2 %0,%1,%2;" : "=l"(d) : "l"(a), "l"(b)); return d;
}
__device__ __forceinline__ u64 fadd2(u64 a, u64 b) {
    u64 d; asm("add.rn.f32x2 %0,%1,%2;" : "=l"(d) : "l"(a), "l"(b)); return d;
}
__device__ __forceinline__ u64 fsub2(u64 a, u64 b) {
    u64 d; asm("sub.rn.f32x2 %0,%1,%2;" : "=l"(d) : "l"(a), "l"(b)); return d;
}

// ---------------------------------------------------------------------------
// KA: fused launch, 128 threads.
//   blocks [0,2048):    forward w-DFT with mirror + quarter-wave folding.
//   blocks [2048,2560): tiled weight transpose -> [blk][m1][kx][ci][co].
//   block  2560:        twiddle tables (incl. k5 parity-pair stw table).
// ---------------------------------------------------------------------------
__global__ __launch_bounds__(128) void kA(const float* __restrict__ x,
                                          const float* __restrict__ wr,
                                          const float* __restrict__ wi) {
    const int bid = blockIdx.x, t = threadIdx.x;

    if (bid < 2048) {
        __shared__ __align__(16) float4 seE[64 * 8], seO[64 * 8];
        __shared__ __align__(16) float4 soE[64 * 8], soO[64 * 8];
        __shared__ __align__(16) float4 stab[256];
        __shared__ __align__(16) float4 sx0[8], sx64[8], sx128[8], sx192[8];
        const float4* xb = (const float4*)(x + (size_t)bid * 8192);

        for (int i = t; i < 256; i += 128) {
            float s, c; sincospif((float)i * (1.0f / 128.0f), &s, &c);
            stab[i] = make_float4(c, c, s, s);
        }
        for (int i = t; i < 504; i += 128) {
            const int w = 1 + (i >> 3), cq = i & 7;
            const float4 a = xb[w * 8 + cq];            // x[w]
            const float4 b = xb[(256 - w) * 8 + cq];    // x[256-w]
            const float4 c = xb[(128 - w) * 8 + cq];    // x[128-w]
            const float4 d = xb[(128 + w) * 8 + cq];    // x[128+w]
            const int ix = w * 8 + cq;
            seE[ix] = make_float4(a.x + b.x + c.x + d.x, a.y + b.y + c.y + d.y,
                                  a.z + b.z + c.z + d.z, a.w + b.w + c.w + d.w);
            seO[ix] = make_float4(a.x + b.x - c.x - d.x, a.y + b.y - c.y - d.y,
                                  a.z + b.z - c.z - d.z, a.w + b.w - c.w - d.w);
            soE[ix] = make_float4(a.x - b.x - c.x + d.x, a.y - b.y - c.y + d.y,
                                  a.z - b.z - c.z + d.z, a.w - b.w - c.w + d.w);
            soO[ix] = make_float4(a.x - b.x + c.x - d.x, a.y - b.y + c.y - d.y,
                                  a.z - b.z + c.z - d.z, a.w - b.w + c.w - d.w);
        }
        if (t < 8) {
            sx0[t] = xb[t]; sx64[t] = xb[512 + t];
            sx128[t] = xb[1024 + t]; sx192[t] = xb[1536 + t];
        }
        __syncthreads();

        const int kx = t >> 3, cq = t & 7;
        const int odd = kx & 1;
        const float s64 = (kx & 2) ? -1.0f : 1.0f;
        const u64 s64v = pack2(s64, s64);
        const u64x2 X0   = *(const u64x2*)&sx0[cq];
        const u64x2 X64  = *(const u64x2*)&sx64[cq];
        const u64x2 X128 = *(const u64x2*)&sx128[cq];
        const u64x2 X192 = *(const u64x2*)&sx192[cq];
        u64 re0, re1, im0, im1;
        if (!odd) {
            re0 = ffma2(fadd2(X64.x, X192.x), s64v, fadd2(X0.x, X128.x));
            re1 = ffma2(fadd2(X64.y, X192.y), s64v, fadd2(X0.y, X128.y));
            im0 = 0; im1 = 0;
        } else {
            re0 = fsub2(X0.x, X128.x);
            re1 = fsub2(X0.y, X128.y);
            im0 = fmul2(fsub2(X64.x, X192.x), s64v);
            im1 = fmul2(fsub2(X64.y, X192.y), s64v);
        }
        const float4* pe = (odd ? seO : seE) + cq;
        const float4* po = (odd ? soO : soE) + cq;
        int m = kx;
#pragma unroll 4
        for (int w = 1; w < 64; w++) {
            const u64x2 ev = *(const u64x2*)(pe + w * 8);
            const u64x2 ov = *(const u64x2*)(po + w * 8);
            const u64x2 tv = *(const u64x2*)&stab[m];
            m = (m + kx) & 255;
            re0 = ffma2(ev.x, tv.x, re0); re1 = ffma2(ev.y, tv.x, re1);
            im0 = ffma2(ov.x, tv.y, im0); im1 = ffma2(ov.y, tv.y, im1);
        }
        const int b = bid >> 8, h = bid & 255;
        const size_t o4 = ((size_t)((b * 16 + kx) * 256 + h)) * 8 + cq;
        const float2 r0 = unpack2(re0), r1 = unpack2(re1);
        ((float4*)g_Tre)[o4] = make_float4(r0.x, r0.y, r1.x, r1.y);
        const u64 n1 = pack2(-1.0f, -1.0f);
        const float2 i0 = unpack2(fmul2(im0, n1)), i1 = unpack2(fmul2(im1, n1));
        ((float4*)g_Tim)[o4] = make_float4(i0.x, i0.y, i1.x, i1.y);

    } else if (bid < 2560) {
        // ---- tiled transpose: [ci*32+co][m1*16+kx] -> [m1*16+kx][ci*32+co] ----
        __shared__ float sw[32][33], sv[32][33];
        const int tt = bid - 2048;
        const int blkw = tt >> 8, tile = tt & 255;
        const int tr = tile >> 3, tc = tile & 7;
        const int rr = t >> 5, c = t & 31;
        const float* srcR = wr + blkw * 262144;
        const float* srcI = wi + blkw * 262144;
#pragma unroll
        for (int ph = 0; ph < 8; ph++) {
            const int rl = ph * 4 + rr;
            const int row = tr * 32 + rl, col = tc * 32 + c;
            sw[rl][c] = srcR[row * 256 + col];
            sv[rl][c] = srcI[row * 256 + col];
        }
        __syncthreads();
        float* dR = g_wtr + blkw * 262144;
        float* dI = g_wti + blkw * 262144;
#pragma unroll
        for (int ph = 0; ph < 8; ph++) {
            const int cl = ph * 4 + rr;
            const int dcol = tc * 32 + cl, drow = tr * 32 + c;
            dR[dcol * 1024 + drow] = sw[c][cl];
            dI[dcol * 1024 + drow] = sv[c][cl];
        }
    } else {
        for (int i = t; i < 256; i += 128) {
            float s, c; sincospif((float)i * (1.0f / 128.0f), &s, &c);
            g_tab4[i] = make_float4(c, c, s, s);
            g_tab2[i] = make_float2(c, s);
        }
        for (int i = t; i < 520; i += 128) {
            const int w = i >> 3, j = i & 7;
            float s0, c0, s1, c1;
            sincospif((float)((2 * j * w) & 255) * (1.0f / 128.0f), &s0, &c0);
            sincospif((float)(((2 * j + 1) * w) & 255) * (1.0f / 128.0f), &s1, &c1);
            g_stw[i] = make_float4(c0, c1, s0, s1);
        }
    }
}

// ---------------------------------------------------------------------------
// K2: forward DFT over h, conjugate-pair generators + quarter-wave folding.
// Prep phase uses float4 loads over channel quads (half the LDG count).
// grid (16 kx, 2 ch, 8 b) = 256 blocks, 136 threads: p = t>>3 (0..16), cp = t&7.
// ---------------------------------------------------------------------------
__global__ __launch_bounds__(136) void k2_dft_h() {
    __shared__ __align__(16) float4 sAe[64 * 8], sAo[64 * 8];   // {cosdata(Er), sindata(Oi)}
    __shared__ __align__(16) float4 sBe[64 * 8], sBo[64 * 8];   // {cosdata(Ei), sindata(-Or)}
    __shared__ __align__(16) float4 stab[256];
    __shared__ __align__(16) float4 sT0[8], sT128[8], sA64[8], sB64[8];
    const int t = threadIdx.x;
    const int kx = blockIdx.x, ch = blockIdx.y, b = blockIdx.z;
    const float* srcR = g_Tre + ((size_t)(b * 16 + kx) * 256) * 32 + ch * 16;
    const float* srcI = g_Tim + ((size_t)(b * 16 + kx) * 256) * 32 + ch * 16;

    for (int i = t; i < 256; i += 136) stab[i] = g_tab4[i];
    for (int i = t; i < 252; i += 136) {
        const int h = 1 + (i >> 2), cq = i & 3;       // channel quad: local ch 4cq..4cq+3
        const float4 ar = *(const float4*)&srcR[h * 32 + cq * 4];
        const float4 br = *(const float4*)&srcR[(256 - h) * 32 + cq * 4];
        const float4 ai = *(const float4*)&srcI[h * 32 + cq * 4];
        const float4 bi = *(const float4*)&srcI[(256 - h) * 32 + cq * 4];
        const float4 cr = *(const float4*)&srcR[(128 - h) * 32 + cq * 4];
        const float4 dr = *(const float4*)&srcR[(128 + h) * 32 + cq * 4];
        const float4 ci = *(const float4*)&srcI[(128 - h) * 32 + cq * 4];
        const float4 di = *(const float4*)&srcI[(128 + h) * 32 + cq * 4];
        // 4-wide folds
        const float4 Er   = make_float4(ar.x + br.x, ar.y + br.y, ar.z + br.z, ar.w + br.w);
        const float4 Erp  = make_float4(cr.x + dr.x, cr.y + dr.y, cr.z + dr.z, cr.w + dr.w);
        const float4 Oi   = make_float4(ai.x - bi.x, ai.y - bi.y, ai.z - bi.z, ai.w - bi.w);
        const float4 Oip  = make_float4(ci.x - di.x, ci.y - di.y, ci.z - di.z, ci.w - di.w);
        const float4 Ei   = make_float4(ai.x + bi.x, ai.y + bi.y, ai.z + bi.z, ai.w + bi.w);
        const float4 Eip  = make_float4(ci.x + di.x, ci.y + di.y, ci.z + di.z, ci.w + di.w);
        const float4 nOr  = make_float4(br.x - ar.x, br.y - ar.y, br.z - ar.z, br.w - ar.w);
        const float4 nOrp = make_float4(dr.x - cr.x, dr.y - cr.y, dr.z - cr.z, dr.w - cr.w);
        const int ix = (h << 3) + cq * 2;
        sAe[ix]     = make_float4(Er.x + Erp.x, Er.y + Erp.y, Oi.x - Oip.x, Oi.y - Oip.y);
        sAe[ix + 1] = make_float4(Er.z + Erp.z, Er.w + Erp.w, Oi.z - Oip.z, Oi.w - Oip.w);
        sAo[ix]     = make_float4(Er.x - Erp.x, Er.y - Erp.y, Oi.x + Oip.x, Oi.y + Oip.y);
        sAo[ix + 1] = make_float4(Er.z - Erp.z, Er.w - Erp.w, Oi.z + Oip.z, Oi.w + Oip.w);
        sBe[ix]     = make_float4(Ei.x + Eip.x, Ei.y + Eip.y, nOr.x - nOrp.x, nOr.y - nOrp.y);
        sBe[ix + 1] = make_float4(Ei.z + Eip.z, Ei.w + Eip.w, nOr.z - nOrp.z, nOr.w - nOrp.w);
        sBo[ix]     = make_float4(Ei.x - Eip.x, Ei.y - Eip.y, nOr.x + nOrp.x, nOr.y + nOrp.y);
        sBo[ix + 1] = make_float4(Ei.z - Eip.z, Ei.w - Eip.w, nOr.z + nOrp.z, nOr.w + nOrp.w);
    }
    if (t < 8) {
        sT0[t]   = make_float4(srcR[t * 2], srcR[t * 2 + 1], srcI[t * 2], srcI[t * 2 + 1]);
        sT128[t] = make_float4(srcR[4096 + t * 2], srcR[4096 + t * 2 + 1],
                               srcI[4096 + t * 2], srcI[4096 + t * 2 + 1]);
        const float r64a = srcR[2048 + t * 2],  r64b = srcR[2048 + t * 2 + 1];
        const float r92a = srcR[6144 + t * 2],  r92b = srcR[6144 + t * 2 + 1];
        const float i64a = srcI[2048 + t * 2],  i64b = srcI[2048 + t * 2 + 1];
        const float i92a = srcI[6144 + t * 2],  i92b = srcI[6144 + t * 2 + 1];
        sA64[t] = make_float4(r64a + r92a, r64b + r92b, i64a - i92a, i64b - i92b);
        sB64[t] = make_float4(i64a + i92a, i64b + i92b, r92a - r64a, r92b - r64b);
    }
    __syncthreads();

    const int p = t >> 3, cp = t & 7;
    const int odd = p & 1;
    const float s64 = (p & 2) ? -1.0f : 1.0f;
    const u64 s64v = pack2(s64, s64);
    const u64x2 t0 = *(const u64x2*)&sT0[cp];
    const u64x2 t1 = *(const u64x2*)&sT128[cp];
    const u64x2 a64 = *(const u64x2*)&sA64[cp];
    const u64x2 b64 = *(const u64x2*)&sB64[cp];
    u64 C1, C2, C3, C4;
    if (!odd) {
        C1 = ffma2(a64.x, s64v, fadd2(t0.x, t1.x)); C2 = 0;
        C3 = ffma2(b64.x, s64v, fadd2(t0.y, t1.y)); C4 = 0;
    } else {
        C1 = fsub2(t0.x, t1.x); C2 = fmul2(a64.y, s64v);
        C3 = fsub2(t0.y, t1.y); C4 = fmul2(b64.y, s64v);
    }
    const float4* pA = (odd ? sAo : sAe) + cp;
    const float4* pB = (odd ? sBo : sBe) + cp;
    int m = p;
#pragma unroll 4
    for (int h = 1; h < 64; h++) {
        const u64x2 A  = *(const u64x2*)(pA + h * 8);
        const u64x2 Bv = *(const u64x2*)(pB + h * 8);
        const u64x2 tv = *(const u64x2*)&stab[m];
        m = (m + p) & 255;
        C1 = ffma2(A.x, tv.x, C1);  C2 = ffma2(A.y, tv.y, C2);
        C3 = ffma2(Bv.x, tv.x, C3); C4 = ffma2(Bv.y, tv.y, C4);
    }
    const int c = ch * 16 + cp * 2;
    if (p < 16) {                                   // X(+p) -> row p
        const size_t ix = (size_t)(p * 16 + kx) * 256 + b * 32 + c;
        *(float2*)&g_Xre[ix] = unpack2(fadd2(C1, C2));
        *(float2*)&g_Xim[ix] = unpack2(fadd2(C3, C4));
    }
    if (p >= 1) {                                   // X(-p) -> row 32-p
        const size_t ix = (size_t)((32 - p) * 16 + kx) * 256 + b * 32 + c;
        *(float2*)&g_Xre[ix] = unpack2(fsub2(C1, C2));
        *(float2*)&g_Xim[ix] = unpack2(fsub2(C3, C4));
    }
}

// ---------------------------------------------------------------------------
// K34: fused channel mix + inverse h-DFT per (kx, b) tile.
// grid (16 kx, 8 b) = 128 blocks, 1024 threads.
// ---------------------------------------------------------------------------
__global__ __launch_bounds__(1024) void k34() {
    __shared__ __align__(16) float4 stab[256];
    __shared__ __align__(16) float sXr[1024], sXi[1024];   // [p][c]
    __shared__ __align__(16) float sYr[1024], sYi[1024];   // [p][co]
    const int t = threadIdx.x;
    const int kx = blockIdx.x, b = blockIdx.y;

    if (t < 256) stab[t] = g_tab4[t];
    {
        const int p = t >> 5, c = t & 31;
        const size_t src = (size_t)(p * 16 + kx) * 256 + b * 32 + c;
        sXr[t] = g_Xre[src];
        sXi[t] = g_Xim[src];
    }
    __syncthreads();

    // ---- Phase 1: channel mix ----
    {
        const int p = t >> 5, co = t & 31;
        const int blk = p >> 4, m1 = p & 15;
        const int base = ((blk * 16 + m1) * 16 + kx) * 1024 + co;
        float accR = 0.f, accI = 0.f;
#pragma unroll
        for (int ci = 0; ci < 32; ci++) {
            const float Xr = sXr[p * 32 + ci], Xi = sXi[p * 32 + ci];
            const float Wr = g_wtr[base + ci * 32];
            const float Wi = g_wti[base + ci * 32];
            accR += Xr * Wr - Xi * Wi;
            accI += Xr * Wi + Xi * Wr;
        }
        sYr[t] = accR;
        sYi[t] = accI;
    }
    __syncthreads();

    // ---- Phase 2: inverse DFT over h, parity-split quad outputs ----
    const int hl = t >> 4, cc = (t >> 3) & 1, cp = t & 7;
    const int h = hl + 1;                        // 1..64
    const int yoff = cc * 16 + cp * 2;
    u64 RcE = 0, RcO = 0, RsE = 0, RsO = 0, IsE = 0, IsO = 0, IcE = 0, IcO = 0;

    int m = 0;                                   // p=0..15: f = p
#pragma unroll 1
    for (int p = 0; p < 16; p += 2) {
        const u64x2 t0 = *(const u64x2*)&stab[m]; m = (m + h) & 255;
        const u64x2 t1 = *(const u64x2*)&stab[m]; m = (m + h) & 255;
        const u64 Yr0 = *(const u64*)&sYr[p * 32 + yoff];
        const u64 Yi0 = *(const u64*)&sYi[p * 32 + yoff];
        const u64 Yr1 = *(const u64*)&sYr[(p + 1) * 32 + yoff];
        const u64 Yi1 = *(const u64*)&sYi[(p + 1) * 32 + yoff];
        RcE = ffma2(Yr0, t0.x, RcE); RsE = ffma2(Yi0, t0.y, RsE);
        IsE = ffma2(Yr0, t0.y, IsE); IcE = ffma2(Yi0, t0.x, IcE);
        RcO = ffma2(Yr1, t1.x, RcO); RsO = ffma2(Yi1, t1.y, RsO);
        IsO = ffma2(Yr1, t1.y, IsO); IcO = ffma2(Yi1, t1.x, IcO);
    }
    m = (4096 - 16 * h) & 255;                   // p=16..31: f = p-32 (same parity as p)
#pragma unroll 1
    for (int p = 16; p < 32; p += 2) {
        const u64x2 t0 = *(const u64x2*)&stab[m]; m = (m + h) & 255;
        const u64x2 t1 = *(const u64x2*)&stab[m]; m = (m + h) & 255;
        const u64 Yr0 = *(const u64*)&sYr[p * 32 + yoff];
        const u64 Yi0 = *(const u64*)&sYi[p * 32 + yoff];
        const u64 Yr1 = *(const u64*)&sYr[(p + 1) * 32 + yoff];
        const u64 Yi1 = *(const u64*)&sYi[(p + 1) * 32 + yoff];
        RcE = ffma2(Yr0, t0.x, RcE); RsE = ffma2(Yi0, t0.y, RsE);
        IsE = ffma2(Yr0, t0.y, IsE); IcE = ffma2(Yi0, t0.x, IcE);
        RcO = ffma2(Yr1, t1.x, RcO); RsO = ffma2(Yi1, t1.y, RsO);
        IsO = ffma2(Yr1, t1.y, IsO); IcO = ffma2(Yi1, t1.x, IcO);
    }

    const u64 Rcs = fadd2(RcE, RcO), Rcd = fsub2(RcE, RcO);
    const u64 Rss = fadd2(RsE, RsO), Rsd = fsub2(RsE, RsO);
    const u64 Iss = fadd2(IsE, IsO), Isd = fsub2(IsE, IsO);
    const u64 Ics = fadd2(IcE, IcO), Icd = fsub2(IcE, IcO);

    const float sc = (kx == 0 ? 1.0f : 2.0f) * (1.0f / 65536.0f);
    const u64 scl = pack2(sc, sc);
    const size_t rowbase = ((size_t)(b * 256) * 16 + kx) * 32 + yoff;

    *(float2*)&g_Gre[rowbase + (size_t)h * 512] = unpack2(fmul2(fsub2(Rcs, Rss), scl));
    *(float2*)&g_Gim[rowbase + (size_t)h * 512] = unpack2(fmul2(fadd2(Iss, Ics), scl));
    *(float2*)&g_Gre[rowbase + (size_t)(128 + h) * 512] = unpack2(fmul2(fsub2(Rcd, Rsd), scl));
    *(float2*)&g_Gim[rowbase + (size_t)(128 + h) * 512] = unpack2(fmul2(fadd2(Isd, Icd), scl));
    if (h < 64) {
        *(float2*)&g_Gre[rowbase + (size_t)(256 - h) * 512] = unpack2(fmul2(fadd2(Rcs, Rss), scl));
        *(float2*)&g_Gim[rowbase + (size_t)(256 - h) * 512] = unpack2(fmul2(fsub2(Ics, Iss), scl));
        *(float2*)&g_Gre[rowbase + (size_t)(128 - h) * 512] = unpack2(fmul2(fadd2(Rcd, Rsd), scl));
        *(float2*)&g_Gim[rowbase + (size_t)(128 - h) * 512] = unpack2(fmul2(fsub2(Icd, Isd), scl));
    } else {
        u64 ZrE = 0, ZrO = 0, ZiE = 0, ZiO = 0;
#pragma unroll 1
        for (int p = 0; p < 32; p += 2) {
            const u64 Yr0 = *(const u64*)&sYr[p * 32 + yoff];
            const u64 Yi0 = *(const u64*)&sYi[p * 32 + yoff];
            const u64 Yr1 = *(const u64*)&sYr[(p + 1) * 32 + yoff];
            const u64 Yi1 = *(const u64*)&sYi[(p + 1) * 32 + yoff];
            ZrE = fadd2(ZrE, Yr0); ZiE = fadd2(ZiE, Yi0);
            ZrO = fadd2(ZrO, Yr1); ZiO = fadd2(ZiO, Yi1);
        }
        *(float2*)&g_Gre[rowbase] = unpack2(fmul2(fadd2(ZrE, ZrO), scl));
        *(float2*)&g_Gim[rowbase] = unpack2(fmul2(fadd2(ZiE, ZiO), scl));
        *(float2*)&g_Gre[rowbase + (size_t)128 * 512] = unpack2(fmul2(fsub2(ZrE, ZrO), scl));
        *(float2*)&g_Gim[rowbase + (size_t)128 * 512] = unpack2(fmul2(fsub2(ZiE, ZiO), scl));
    }
}

// ---------------------------------------------------------------------------
// K5: inverse DFT over w, parity k-pairs: lane0 = even k, lane1 = odd k.
// One (C,S) accumulation (8+8 ffma2, 8 LDS.128) -> FOUR outputs:
//   out(w) = Cs-Ss, out(256-w) = Cs+Ss, out(128+w) = Cd-Sd, out(128-w) = Cd+Sd
// grid 2048 (b*256+h), 256 threads = co(32) x wg(8).
// ---------------------------------------------------------------------------
__device__ __forceinline__ void k5_body(const float4* stw, const u64* Gr, const u64* Gi,
                                        float* ob, int w, int co) {
    u64 C = 0, S = 0;
    const u64x2* tw = (const u64x2*)&stw[w * 8];
#pragma unroll
    for (int j = 0; j < 8; j++) {
        const u64x2 v = tw[j];
        C = ffma2(Gr[j], v.x, C);
        S = ffma2(Gi[j], v.y, S);
    }
    const float2 c2 = unpack2(C), s2 = unpack2(S);
    const float Cs = c2.x + c2.y, Cd = c2.x - c2.y;
    const float Ss = s2.x + s2.y, Sd = s2.x - s2.y;
    ob[w * 32 + co]                   = Cs - Ss;
    ob[(((256 - w) & 255)) * 32 + co] = Cs + Ss;
    ob[(128 + w) * 32 + co]           = Cd - Sd;
    ob[(128 - w) * 32 + co]           = Cd + Sd;
}

__global__ __launch_bounds__(256) void k5_idft_w(float* __restrict__ out) {
    __shared__ __align__(16) float4 stw[65 * 8];   // [w][j] (c2j, c2j1, s2j, s2j1)
    const int t = threadIdx.x;
    const int blk = blockIdx.x;                     // b*256 + h

    for (int i = t; i < 520; i += 256) stw[i] = g_stw[i];
    const int co = t & 31, wg = t >> 5;
    u64 Gr[8], Gi[8];
    {
        const float* pr = g_Gre + (size_t)blk * 512 + co;
        const float* pi = g_Gim + (size_t)blk * 512 + co;
#pragma unroll
        for (int j = 0; j < 8; j++) {
            Gr[j] = pack2(pr[(2 * j) * 32], pr[(2 * j + 1) * 32]);
            Gi[j] = pack2(pi[(2 * j) * 32], pi[(2 * j + 1) * 32]);
        }
    }
    __syncthreads();

    float* ob = out + (size_t)blk * 8192;
#pragma unroll 1
    for (int j = 0; j < 8; j++) k5_body(stw, Gr, Gi, ob, wg + 8 * j, co);
    if (wg == 0) k5_body(stw, Gr, Gi, ob, 64, co);
}

// ---------------------------------------------------------------------------
extern "C" void kernel_launch(void* const* d_in, const int* in_sizes, int n_in,
                              void* d_out, int out_size) {
    (void)n_in; (void)out_size; (void)in_sizes;
    const float* x  = (const float*)d_in[0];
    const float* wr = (const float*)d_in[1];
    const float* wi = (const float*)d_in[2];
    float* out = (float*)d_out;

    kA<<<2561, 128>>>(x, wr, wi);
    k2_dft_h<<<dim3(16, 2, 8), 136>>>();
    k34<<<dim3(16, 8), 1024>>>();
    k5_idft_w<<<2048, 256>>>(out);
}